// round 6
// baseline (speedup 1.0000x reference)
#include <cuda_runtime.h>

// Shapes (fixed by the problem)
#define B_      16
#define S_      4096
#define D_      512
#define PE_DIM_ 256

// Scratch: per-batch valid lengths (count of mask==0 along S)
__device__ int g_lengths[B_];

// ---------------------------------------------------------------------------
// Kernel 1: lengths[b] = sum_s (mask[b,s] == 0).  16 blocks x 256 threads.
// ---------------------------------------------------------------------------
__global__ void lengths_kernel(const int* __restrict__ mask) {
    int b = blockIdx.x;
    const int4* m = reinterpret_cast<const int4*>(mask + b * S_);
    int cnt = 0;
    for (int i = threadIdx.x; i < S_ / 4; i += blockDim.x) {
        int4 v = m[i];
        cnt += (v.x == 0) + (v.y == 0) + (v.z == 0) + (v.w == 0);
    }
    // intra-warp reduce
    #pragma unroll
    for (int o = 16; o > 0; o >>= 1)
        cnt += __shfl_down_sync(0xFFFFFFFFu, cnt, o);

    __shared__ int ws[8];
    if ((threadIdx.x & 31) == 0) ws[threadIdx.x >> 5] = cnt;
    __syncthreads();
    if (threadIdx.x < 8) {
        cnt = ws[threadIdx.x];
        #pragma unroll
        for (int o = 4; o > 0; o >>= 1)
            cnt += __shfl_down_sync(0x000000FFu, cnt, o);
        if (threadIdx.x == 0) g_lengths[b] = cnt;
    }
}

// ---------------------------------------------------------------------------
// Kernel 2: out[b,s,d] = x[b,s,d] + pe[s, d%256]
//                        + (s < L[b] ? pe[L[b]-1-s, 255-(d%256)] : 0)
// One thread per float4 (4 consecutive d).
// ---------------------------------------------------------------------------
__global__ void pe_add_kernel(const float4* __restrict__ x,
                              const float*  __restrict__ pe,
                              float4*       __restrict__ out) {
    unsigned i = blockIdx.x * blockDim.x + threadIdx.x;   // < B*S*D/4 = 2^23
    // decode: d4 in [0,128), s in [0,4096), b in [0,16)
    int d4 = i & 127;
    int s  = (i >> 7) & 4095;
    int b  = i >> 19;

    int c = (d4 << 2) & (PE_DIM_ - 1);    // column within pe (0..252, step 4)

    float4 xv = x[i];
    float4 bp = *reinterpret_cast<const float4*>(pe + (size_t)s * PE_DIM_ + c);

    float4 r;
    r.x = xv.x + bp.x;
    r.y = xv.y + bp.y;
    r.z = xv.z + bp.z;
    r.w = xv.w + bp.w;

    int L = g_lengths[b];
    if (s < L) {
        int rrow = L - 1 - s;   // >= 0 guaranteed by s < L
        float4 rp = *reinterpret_cast<const float4*>(
            pe + (size_t)rrow * PE_DIM_ + (PE_DIM_ - 4 - c));
        // feature-reversed: column 255-c maps to rp.w, 254-c -> rp.z, ...
        r.x += rp.w;
        r.y += rp.z;
        r.z += rp.y;
        r.w += rp.x;
    }
    out[i] = r;
}

// ---------------------------------------------------------------------------
// Launch
// ---------------------------------------------------------------------------
extern "C" void kernel_launch(void* const* d_in, const int* in_sizes, int n_in,
                              void* d_out, int out_size) {
    const float* x    = (const float*)d_in[0];   // (16, 4096, 512) f32
    const int*   mask = (const int*)  d_in[1];   // (16, 4096) i32
    const float* pe   = (const float*)d_in[2];   // (5000, 256) f32
    float*       out  = (float*)d_out;           // (16, 4096, 512) f32

    lengths_kernel<<<B_, 256>>>(mask);

    unsigned total4 = (unsigned)(out_size / 4);  // 8,388,608
    int threads = 256;
    unsigned blocks = (total4 + threads - 1) / threads;
    pe_add_kernel<<<blocks, threads>>>((const float4*)x, pe, (float4*)out);
}

// round 7
// speedup vs baseline: 1.0688x; 1.0688x over previous
#include <cuda_runtime.h>

// Shapes (fixed by the problem)
#define B_      16
#define S_      4096
#define D_      512
#define PE_DIM_ 256

// Scratch: per-batch valid lengths (count of mask==0 along S)
__device__ int g_lengths[B_];

// ---------------------------------------------------------------------------
// Kernel 1: lengths[b] = sum_s (mask[b,s] == 0).
// 16 blocks x 1024 threads: each thread loads exactly one int4 -> a single
// DRAM round-trip instead of 4 serialized rounds.
// ---------------------------------------------------------------------------
__global__ void lengths_kernel(const int* __restrict__ mask) {
    int b = blockIdx.x;
    const int4* m = reinterpret_cast<const int4*>(mask + b * S_);
    int4 v = m[threadIdx.x];                       // 1024 threads * 4 = 4096
    int cnt = (v.x == 0) + (v.y == 0) + (v.z == 0) + (v.w == 0);

    #pragma unroll
    for (int o = 16; o > 0; o >>= 1)
        cnt += __shfl_down_sync(0xFFFFFFFFu, cnt, o);

    __shared__ int ws[32];
    if ((threadIdx.x & 31) == 0) ws[threadIdx.x >> 5] = cnt;
    __syncthreads();
    if (threadIdx.x < 32) {
        cnt = ws[threadIdx.x];
        #pragma unroll
        for (int o = 16; o > 0; o >>= 1)
            cnt += __shfl_down_sync(0xFFFFFFFFu, cnt, o);
        if (threadIdx.x == 0) g_lengths[b] = cnt;
    }
}

// ---------------------------------------------------------------------------
// Kernel 2: out[b,s,d] = x[b,s,d] + pe[s, d%256]
//                        + (s < L[b] ? pe[L[b]-1-s, 255-(d%256)] : 0)
// 2 float4 per thread (i and i+blockDim.x, both coalesced) to raise
// front-batched MLP. Streaming hints (__ldcs/__stcs) on x/out so the 5 MB
// pe table stays L2-resident against the 268 MB stream.
// ---------------------------------------------------------------------------
__device__ __forceinline__ float4 pe_elem(unsigned i,
                                          const float4* __restrict__ x,
                                          const float*  __restrict__ pe,
                                          int L) {
    int d4 = i & 127;
    int s  = (i >> 7) & 4095;

    int c = (d4 << 2) & (PE_DIM_ - 1);

    float4 xv = __ldcs(x + i);                     // no reuse: evict-first
    float4 bp = *reinterpret_cast<const float4*>(pe + (size_t)s * PE_DIM_ + c);

    float4 r;
    r.x = xv.x + bp.x;
    r.y = xv.y + bp.y;
    r.z = xv.z + bp.z;
    r.w = xv.w + bp.w;

    if (s < L) {
        int rrow = L - 1 - s;                      // >= 0 guaranteed by s < L
        float4 rp = *reinterpret_cast<const float4*>(
            pe + (size_t)rrow * PE_DIM_ + (PE_DIM_ - 4 - c));
        // feature-reversed: column 255-c -> rp.w, 254-c -> rp.z, ...
        r.x += rp.w;
        r.y += rp.z;
        r.z += rp.y;
        r.w += rp.x;
    }
    return r;
}

__global__ void pe_add_kernel(const float4* __restrict__ x,
                              const float*  __restrict__ pe,
                              float4*       __restrict__ out) {
    unsigned i0 = blockIdx.x * (blockDim.x * 2u) + threadIdx.x;
    unsigned i1 = i0 + blockDim.x;
    // Block covers 512 consecutive float4s; 2^19 (batch span) is a multiple
    // of 512, so the whole block sits inside one batch -> one L load.
    int b = i0 >> 19;
    int L = __ldg(&g_lengths[b]);

    float4 r0 = pe_elem(i0, x, pe, L);
    float4 r1 = pe_elem(i1, x, pe, L);

    __stcs(out + i0, r0);
    __stcs(out + i1, r1);
}

// ---------------------------------------------------------------------------
// Launch
// ---------------------------------------------------------------------------
extern "C" void kernel_launch(void* const* d_in, const int* in_sizes, int n_in,
                              void* d_out, int out_size) {
    const float* x    = (const float*)d_in[0];   // (16, 4096, 512) f32
    const int*   mask = (const int*)  d_in[1];   // (16, 4096) i32
    const float* pe   = (const float*)d_in[2];   // (5000, 256) f32
    float*       out  = (float*)d_out;           // (16, 4096, 512) f32

    lengths_kernel<<<B_, 1024>>>(mask);

    unsigned total4 = (unsigned)(out_size / 4);  // 8,388,608
    int threads = 256;
    unsigned blocks = total4 / (threads * 2);    // 16384, exact
    pe_add_kernel<<<blocks, threads>>>((const float4*)x, pe, (float4*)out);
}